// round 13
// baseline (speedup 1.0000x reference)
#include <cuda_runtime.h>
#include <cstdint>
#include <cstddef>

#define HH   32
#define SQ   2048
#define SKK  2048
#define DHH  128
#define BM   64
#define BN   64
#define NTILES (SKK / BN)          // 32
#define VSTR2 132                  // uint32 stride per k2-row in smem (conflict-free LDS.128)
#define LOG2E 1.4426950408889634f

// two half2 V buffers of [32][VSTR2] uint32
#define SMEM_BYTES (2 * 32 * VSTR2 * 4)

// V scratch: k-interleaved half2, COLUMN-PERMUTED:
//   Vh_g[h][k2][p] with p = (n&7)*16 + (n>>3)  holds half2(V[2k2][n], V[2k2+1][n])
__device__ uint32_t Vh_g[(size_t)HH * (SKK / 2) * DHH];   // 16 MB

__device__ __forceinline__ float ex2f(float x) {
    float y;
    asm("ex2.approx.ftz.f32 %0, %1;" : "=f"(y) : "f"(x));
    return y;
}
// pack two fp32 -> half2 with 'lo' in low 16 bits (verified R6-R10)
__device__ __forceinline__ uint32_t packh2(float lo, float hi) {
    uint32_t d;
    asm("cvt.rn.f16x2.f32 %0, %1, %2;" : "=r"(d) : "f"(hi), "f"(lo));
    return d;
}
__device__ __forceinline__ void cp16(uint32_t dst, const void* src) {
    asm volatile("cp.async.cg.shared.global [%0], [%1], 16;\n" :: "r"(dst), "l"(src));
}

// ---- kernel 1: V fp32 -> permuted interleaved half2 scratch (unchanged from R10) ----
__global__ __launch_bounds__(256)
void convert_v_kernel(const float* __restrict__ value)
{
    const int idx = blockIdx.x * 256 + threadIdx.x;
    const int lr = idx & 7;
    const int tt = (idx >> 3) & 3;
    const int k2 = (idx >> 5) & 1023;
    const int h  = idx >> 15;
    const float* v0 = value + ((size_t)h * SKK + 2 * (size_t)k2) * DHH;
    const float* v1 = v0 + DHH;
    const int n0 = tt * 32 + lr;
    uint4 o;
    o.x = packh2(v0[n0],      v1[n0]);
    o.y = packh2(v0[n0 + 8],  v1[n0 + 8]);
    o.z = packh2(v0[n0 + 16], v1[n0 + 16]);
    o.w = packh2(v0[n0 + 24], v1[n0 + 24]);
    *(uint4*)&Vh_g[((size_t)h * 1024 + k2) * DHH + lr * 16 + tt * 4] = o;
}

// ---- kernel 2: fused sink-softmax @ V  (BM=64: warp owns 16 rows; 3 CTAs/SM) ----
__global__ __launch_bounds__(128, 3)
void attn_sink_kernel(const float* __restrict__ logits,
                      const float* __restrict__ sinks,
                      float* __restrict__ out)
{
    extern __shared__ uint32_t smemh[];   // [2][32][VSTR2]

    const int qt   = blockIdx.x;      // 0..31
    const int h    = blockIdx.y;      // 0..31
    const int tid  = threadIdx.x;
    const int lane = tid & 31;
    const int w    = tid >> 5;        // warp 0..3 owns rows [w*16, w*16+16)
    const int lc   = lane & 3;
    const int lr   = lane >> 2;
    const int cb   = 2 * lc;

    const float* Lg = logits + ((size_t)h * SQ + (size_t)qt * BM) * SKK;

    const uint32_t sbase = (uint32_t)__cvta_generic_to_shared(smemh);

    // A row pointers: rows r0, r0+8
    const int r0 = w * 16 + lr;
    const float* Ar0 = Lg + (size_t)r0 * SKK;
    const float* Ar1 = Lg + (size_t)(r0 + 8) * SKK;

    // ---- V staging (identical to R10): thread -> k2-row tid>>2, quarter (tid&3)*32 ----
    const int k2l = tid >> 2, nq = tid & 3;
    const uint32_t* Vsrc0 = &Vh_g[((size_t)h * 1024 + k2l) * DHH + nq * 32];
    const uint32_t Vdst0 = sbase + (uint32_t)(k2l * VSTR2 + nq * 32) * 4u;

#define STAGE_V(stg, ktn)                                                          \
    do {                                                                           \
        const uint32_t* s_ = Vsrc0 + (size_t)(ktn) * 32 * DHH;                     \
        uint32_t d_ = Vdst0 + (uint32_t)((stg) * 32 * VSTR2) * 4u;                 \
        _Pragma("unroll")                                                          \
        for (int i_ = 0; i_ < 8; ++i_) cp16(d_ + i_ * 16u, s_ + i_ * 4);           \
        asm volatile("cp.async.commit_group;\n");                                  \
    } while (0)

    STAGE_V(0, 0);

    float2 rawA[8], rawB[8];

#define LDG_A(dst, h_, ktn)                                                        \
    do {                                                                           \
        _Pragma("unroll")                                                          \
        for (int kk_ = 0; kk_ < 2; ++kk_) {                                        \
            const int c_ = (ktn) * BN + ((h_) * 2 + kk_) * 16 + cb;                \
            float2* d_ = &dst[kk_ * 4];                                            \
            d_[0] = *(const float2*)(Ar0 + c_);                                    \
            d_[1] = *(const float2*)(Ar1 + c_);                                    \
            d_[2] = *(const float2*)(Ar0 + c_ + 8);                                \
            d_[3] = *(const float2*)(Ar1 + c_ + 8);                                \
        }                                                                          \
    } while (0)

#define EXP_PACK(raw, P)                                                           \
    do {                                                                           \
        _Pragma("unroll")                                                          \
        for (int kk_ = 0; kk_ < 2; ++kk_) {                                        \
            float2* q_ = &raw[kk_ * 4];                                            \
            float e00 = ex2f(q_[0].x * LOG2E), e01 = ex2f(q_[0].y * LOG2E);        \
            float e10 = ex2f(q_[1].x * LOG2E), e11 = ex2f(q_[1].y * LOG2E);        \
            float e20 = ex2f(q_[2].x * LOG2E), e21 = ex2f(q_[2].y * LOG2E);        \
            float e30 = ex2f(q_[3].x * LOG2E), e31 = ex2f(q_[3].y * LOG2E);        \
            psum[0] += (e00 + e01) + (e20 + e21);                                  \
            psum[1] += (e10 + e11) + (e30 + e31);                                  \
            P[kk_][0] = packh2(e00, e01);                                          \
            P[kk_][1] = packh2(e10, e11);                                          \
            P[kk_][2] = packh2(e20, e21);                                          \
            P[kk_][3] = packh2(e30, e31);                                          \
        }                                                                          \
    } while (0)

    // B via LDS.128: 4 consecutive nt per load (permuted layout), conflict-free
#define MMA_HALF(P, kbase)                                                         \
    do {                                                                           \
        _Pragma("unroll")                                                          \
        for (int kk_ = 0; kk_ < 2; ++kk_) {                                        \
            const uint32_t* vr0 = &Vs[(((kbase) + kk_) * 8 + lc) * VSTR2 + lr * 16]; \
            const uint32_t* vr1 = vr0 + 4 * VSTR2;                                 \
            _Pragma("unroll")                                                      \
            for (int g_ = 0; g_ < 4; ++g_) {                                       \
                uint4 B0 = *(const uint4*)(vr0 + g_ * 4);                          \
                uint4 B1 = *(const uint4*)(vr1 + g_ * 4);                          \
                const uint32_t b0a[4] = {B0.x, B0.y, B0.z, B0.w};                  \
                const uint32_t b1a[4] = {B1.x, B1.y, B1.z, B1.w};                  \
                _Pragma("unroll")                                                  \
                for (int e_ = 0; e_ < 4; ++e_) {                                   \
                    const int nt_ = g_ * 4 + e_;                                   \
                    asm volatile(                                                  \
                        "mma.sync.aligned.m16n8k16.row.col.f32.f16.f16.f32 "       \
                        "{%0,%1,%2,%3}, {%4,%5,%6,%7}, {%8,%9}, {%0,%1,%2,%3};\n"  \
                        : "+f"(acc[nt_][0]), "+f"(acc[nt_][1]),                    \
                          "+f"(acc[nt_][2]), "+f"(acc[nt_][3])                     \
                        : "r"(P[kk_][0]), "r"(P[kk_][1]),                          \
                          "r"(P[kk_][2]), "r"(P[kk_][3]),                          \
                          "r"(b0a[e_]), "r"(b1a[e_]));                             \
                }                                                                  \
            }                                                                      \
        }                                                                          \
    } while (0)

    float acc[16][4];
#pragma unroll
    for (int nt = 0; nt < 16; ++nt) {
        acc[nt][0] = 0.f; acc[nt][1] = 0.f;
        acc[nt][2] = 0.f; acc[nt][3] = 0.f;
    }
    float psum[2] = {0.f, 0.f};

    LDG_A(rawA, 0, 0);
    LDG_A(rawB, 1, 0);

    for (int kt = 0; kt < NTILES; ++kt) {
        const int cur = kt & 1;

        __syncthreads();   // readers of buf[cur^1] (prev iter) done before refill

        if (kt + 1 < NTILES) {
            STAGE_V(cur ^ 1, kt + 1);
            asm volatile("cp.async.wait_group 1;\n");
        } else {
            asm volatile("cp.async.wait_group 0;\n");
        }
        __syncthreads();   // buf[cur] visible

        const uint32_t* Vs = smemh + cur * 32 * VSTR2;

        uint32_t P[2][4];

        EXP_PACK(rawA, P);
        if (kt + 1 < NTILES) LDG_A(rawA, 0, kt + 1);
        MMA_HALF(P, 0);

        EXP_PACK(rawB, P);
        if (kt + 1 < NTILES) LDG_A(rawB, 1, kt + 1);
        MMA_HALF(P, 2);
    }

    // ---- reduce row sums over the quad, add sink, normalize ----
#pragma unroll
    for (int j = 0; j < 2; ++j) {
        psum[j] += __shfl_xor_sync(0xffffffffu, psum[j], 1);
        psum[j] += __shfl_xor_sync(0xffffffffu, psum[j], 2);
    }
    const float snk = ex2f(sinks[h] * LOG2E);
    const float inv0 = 1.0f / (psum[0] + snk);
    const float inv1 = 1.0f / (psum[1] + snk);

    float* Ob = out + ((size_t)h * SQ + (size_t)qt * BM) * DHH;
    float* O0 = Ob + (size_t)r0 * DHH + 2 * lc;
    float* O1 = Ob + (size_t)(r0 + 8) * DHH + 2 * lc;
#pragma unroll
    for (int nt = 0; nt < 16; ++nt) {
        *(float2*)(O0 + nt * 8) = make_float2(acc[nt][0] * inv0, acc[nt][1] * inv0);
        *(float2*)(O1 + nt * 8) = make_float2(acc[nt][2] * inv1, acc[nt][3] * inv1);
    }
}

extern "C" void kernel_launch(void* const* d_in, const int* in_sizes, int n_in,
                              void* d_out, int out_size)
{
    const float* logits = (const float*)d_in[0];
    const float* value  = (const float*)d_in[1];
    const float* sinks  = (const float*)d_in[2];
    float* out = (float*)d_out;

    convert_v_kernel<<<(HH * 1024 * 32) / 256, 256>>>(value);

    cudaFuncSetAttribute(attn_sink_kernel,
                         cudaFuncAttributeMaxDynamicSharedMemorySize, SMEM_BYTES);

    dim3 grid(SQ / BM, HH, 1);
    attn_sink_kernel<<<grid, 128, SMEM_BYTES>>>(logits, sinks, out);
}

// round 14
// speedup vs baseline: 1.1904x; 1.1904x over previous
#include <cuda_runtime.h>
#include <cstdint>
#include <cstddef>

#define HH   32
#define SQ   2048
#define SKK  2048
#define DHH  128
#define BM   128
#define BN   64
#define NTILES (SKK / BN)          // 32
#define ASTR  72                   // A smem row stride (floats) -> conflict-free float2 LDS
#define VSTR2 132                  // V smem u32 stride per k2-row (conflict-free LDS.128)
#define ABYTES (BM * ASTR * 4)     // 36864 B per A stage
#define VBYTES (32 * VSTR2 * 4)    // 16896 B per V stage
#define OFFV   (2 * ABYTES)        // 73728
#define SMEM_BYTES (2 * ABYTES + 2 * VBYTES)   // 107520
#define LOG2E 1.4426950408889634f

// V scratch: k-interleaved half2, COLUMN-PERMUTED:
//   Vh_g[h][k2][p] with p = (n&7)*16 + (n>>3)  holds half2(V[2k2][n], V[2k2+1][n])
__device__ uint32_t Vh_g[(size_t)HH * (SKK / 2) * DHH];   // 16 MB

__device__ __forceinline__ float ex2f(float x) {
    float y;
    asm("ex2.approx.ftz.f32 %0, %1;" : "=f"(y) : "f"(x));
    return y;
}
// pack two fp32 -> half2 with 'lo' in low 16 bits (verified R6-R10)
__device__ __forceinline__ uint32_t packh2(float lo, float hi) {
    uint32_t d;
    asm("cvt.rn.f16x2.f32 %0, %1, %2;" : "=r"(d) : "f"(hi), "f"(lo));
    return d;
}
__device__ __forceinline__ void cp16(uint32_t dst, const void* src) {
    asm volatile("cp.async.cg.shared.global [%0], [%1], 16;\n" :: "r"(dst), "l"(src));
}

// ---- kernel 1: V fp32 -> permuted interleaved half2 scratch (unchanged from R10) ----
__global__ __launch_bounds__(256)
void convert_v_kernel(const float* __restrict__ value)
{
    const int idx = blockIdx.x * 256 + threadIdx.x;
    const int lr = idx & 7;
    const int tt = (idx >> 3) & 3;
    const int k2 = (idx >> 5) & 1023;
    const int h  = idx >> 15;
    const float* v0 = value + ((size_t)h * SKK + 2 * (size_t)k2) * DHH;
    const float* v1 = v0 + DHH;
    const int n0 = tt * 32 + lr;
    uint4 o;
    o.x = packh2(v0[n0],      v1[n0]);
    o.y = packh2(v0[n0 + 8],  v1[n0 + 8]);
    o.z = packh2(v0[n0 + 16], v1[n0 + 16]);
    o.w = packh2(v0[n0 + 24], v1[n0 + 24]);
    *(uint4*)&Vh_g[((size_t)h * 1024 + k2) * DHH + lr * 16 + tt * 4] = o;
}

// ---- kernel 2: fused sink-softmax @ V ----
__global__ __launch_bounds__(128)
void attn_sink_kernel(const float* __restrict__ logits,
                      const float* __restrict__ sinks,
                      float* __restrict__ out)
{
    extern __shared__ char smem[];   // [2][128][ASTR] fp32 A | [2][32][VSTR2] u32 V

    const int qt   = blockIdx.x;
    const int h    = blockIdx.y;
    const int tid  = threadIdx.x;
    const int lane = tid & 31;
    const int w    = tid >> 5;        // warp 0..3 owns rows [w*32, w*32+32)
    const int lc   = lane & 3;
    const int lr   = lane >> 2;
    const int cb   = 2 * lc;

    const float* Lg = logits + ((size_t)h * SQ + (size_t)qt * BM) * SKK;

    const uint32_t sbase = (uint32_t)__cvta_generic_to_shared(smem);

    // ---- A staging: thread tid -> row tid, 16 x 16B chunks (64 floats) ----
    const float*  Asrc0 = Lg + (size_t)tid * SKK;
    const uint32_t Adst0 = sbase + (uint32_t)tid * (ASTR * 4);

    // ---- V staging (identical to R10): thread -> k2-row tid>>2, quarter (tid&3)*32 ----
    const int k2l = tid >> 2, nq = tid & 3;
    const uint32_t* Vsrc0 = &Vh_g[((size_t)h * 1024 + k2l) * DHH + nq * 32];
    const uint32_t Vdst0 = sbase + OFFV + (uint32_t)(k2l * VSTR2 + nq * 32) * 4u;

#define STAGE_TILE(stg, ktn)                                                       \
    do {                                                                           \
        const float* as_ = Asrc0 + (ktn) * BN;                                     \
        uint32_t ad_ = Adst0 + (uint32_t)((stg) * ABYTES);                         \
        _Pragma("unroll")                                                          \
        for (int i_ = 0; i_ < 16; ++i_) cp16(ad_ + i_ * 16u, as_ + i_ * 4);        \
        const uint32_t* vs_ = Vsrc0 + (size_t)(ktn) * 32 * DHH;                    \
        uint32_t vd_ = Vdst0 + (uint32_t)((stg) * VBYTES);                         \
        _Pragma("unroll")                                                          \
        for (int i_ = 0; i_ < 8; ++i_) cp16(vd_ + i_ * 16u, vs_ + i_ * 4);         \
        asm volatile("cp.async.commit_group;\n");                                  \
    } while (0)

    STAGE_TILE(0, 0);

    // A fragment row byte-offsets (precomputed): [mi] -> row w*32+mi*16+lr
    const int ro0 = (w * 32 + 0 * 16 + lr) * ASTR;
    const int ro1 = (w * 32 + 1 * 16 + lr) * ASTR;

    // exp/pack straight from A smem (same arithmetic & order as R10's EXP_PACK)
#define EXP_PACK_S(As, h_, P)                                                      \
    do {                                                                           \
        _Pragma("unroll")                                                          \
        for (int mi_ = 0; mi_ < 2; ++mi_)                                          \
        _Pragma("unroll")                                                          \
        for (int kk_ = 0; kk_ < 2; ++kk_) {                                        \
            const int ro_ = mi_ ? ro1 : ro0;                                       \
            const int c_  = ((h_) * 2 + kk_) * 16 + cb;                            \
            float2 x0 = *(const float2*)((As) + ro_ + c_);                         \
            float2 x1 = *(const float2*)((As) + ro_ + 8 * ASTR + c_);              \
            float2 x2 = *(const float2*)((As) + ro_ + c_ + 8);                     \
            float2 x3 = *(const float2*)((As) + ro_ + 8 * ASTR + c_ + 8);          \
            float e00 = ex2f(x0.x * LOG2E), e01 = ex2f(x0.y * LOG2E);              \
            float e10 = ex2f(x1.x * LOG2E), e11 = ex2f(x1.y * LOG2E);              \
            float e20 = ex2f(x2.x * LOG2E), e21 = ex2f(x2.y * LOG2E);              \
            float e30 = ex2f(x3.x * LOG2E), e31 = ex2f(x3.y * LOG2E);              \
            psum[mi_][0] += (e00 + e01) + (e20 + e21);                             \
            psum[mi_][1] += (e10 + e11) + (e30 + e31);                             \
            P[mi_][kk_][0] = packh2(e00, e01);                                     \
            P[mi_][kk_][1] = packh2(e10, e11);                                     \
            P[mi_][kk_][2] = packh2(e20, e21);                                     \
            P[mi_][kk_][3] = packh2(e30, e31);                                     \
        }                                                                          \
    } while (0)

    // B via LDS.128: 4 consecutive nt per load (permuted layout), conflict-free (R10)
#define MMA_HALF(P, kbase)                                                         \
    do {                                                                           \
        _Pragma("unroll")                                                          \
        for (int kk_ = 0; kk_ < 2; ++kk_) {                                        \
            const uint32_t* vr0 = &Vs[(((kbase) + kk_) * 8 + lc) * VSTR2 + lr * 16]; \
            const uint32_t* vr1 = vr0 + 4 * VSTR2;                                 \
            _Pragma("unroll")                                                      \
            for (int g_ = 0; g_ < 4; ++g_) {                                       \
                uint4 B0 = *(const uint4*)(vr0 + g_ * 4);                          \
                uint4 B1 = *(const uint4*)(vr1 + g_ * 4);                          \
                const uint32_t b0a[4] = {B0.x, B0.y, B0.z, B0.w};                  \
                const uint32_t b1a[4] = {B1.x, B1.y, B1.z, B1.w};                  \
                _Pragma("unroll")                                                  \
                for (int e_ = 0; e_ < 4; ++e_) {                                   \
                    const int nt_ = g_ * 4 + e_;                                   \
                    _Pragma("unroll")                                              \
                    for (int mi_ = 0; mi_ < 2; ++mi_) {                            \
                        asm volatile(                                              \
                            "mma.sync.aligned.m16n8k16.row.col.f32.f16.f16.f32 "   \
                            "{%0,%1,%2,%3}, {%4,%5,%6,%7}, {%8,%9}, {%0,%1,%2,%3};\n" \
                            : "+f"(acc[mi_][nt_][0]), "+f"(acc[mi_][nt_][1]),      \
                              "+f"(acc[mi_][nt_][2]), "+f"(acc[mi_][nt_][3])       \
                            : "r"(P[mi_][kk_][0]), "r"(P[mi_][kk_][1]),            \
                              "r"(P[mi_][kk_][2]), "r"(P[mi_][kk_][3]),            \
                              "r"(b0a[e_]), "r"(b1a[e_]));                         \
                    }                                                              \
                }                                                                  \
            }                                                                      \
        }                                                                          \
    } while (0)

    float acc[2][16][4];
#pragma unroll
    for (int mi = 0; mi < 2; ++mi)
#pragma unroll
        for (int nt = 0; nt < 16; ++nt) {
            acc[mi][nt][0] = 0.f; acc[mi][nt][1] = 0.f;
            acc[mi][nt][2] = 0.f; acc[mi][nt][3] = 0.f;
        }
    float psum[2][2] = {{0.f, 0.f}, {0.f, 0.f}};

    for (int kt = 0; kt < NTILES; ++kt) {
        const int cur = kt & 1;

        __syncthreads();   // readers of stage[cur^1] (prev iter) done before refill

        if (kt + 1 < NTILES) {
            STAGE_TILE(cur ^ 1, kt + 1);
            asm volatile("cp.async.wait_group 1;\n");   // tile kt landed
        } else {
            asm volatile("cp.async.wait_group 0;\n");
        }
        __syncthreads();   // stage[cur] visible

        const float*    As = (const float*)(smem + cur * ABYTES);
        const uint32_t* Vs = (const uint32_t*)(smem + OFFV + cur * VBYTES);

        uint32_t P[2][2][4];

        EXP_PACK_S(As, 0, P);
        MMA_HALF(P, 0);

        EXP_PACK_S(As, 1, P);
        MMA_HALF(P, 2);
    }

    // ---- reduce row sums over the quad, add sink, normalize ----
#pragma unroll
    for (int mi = 0; mi < 2; ++mi)
#pragma unroll
        for (int j = 0; j < 2; ++j) {
            psum[mi][j] += __shfl_xor_sync(0xffffffffu, psum[mi][j], 1);
            psum[mi][j] += __shfl_xor_sync(0xffffffffu, psum[mi][j], 2);
        }
    const float snk = ex2f(sinks[h] * LOG2E);
    float inv[2][2];
#pragma unroll
    for (int mi = 0; mi < 2; ++mi) {
        inv[mi][0] = 1.0f / (psum[mi][0] + snk);
        inv[mi][1] = 1.0f / (psum[mi][1] + snk);
    }

    float* Ob = out + ((size_t)h * SQ + (size_t)qt * BM) * DHH;
#pragma unroll
    for (int mi = 0; mi < 2; ++mi) {
        const int r0 = w * 32 + mi * 16 + lr;
        float* O0 = Ob + (size_t)r0 * DHH + 2 * lc;
        float* O1 = Ob + (size_t)(r0 + 8) * DHH + 2 * lc;
#pragma unroll
        for (int nt = 0; nt < 16; ++nt) {
            *(float2*)(O0 + nt * 8) =
                make_float2(acc[mi][nt][0] * inv[mi][0], acc[mi][nt][1] * inv[mi][0]);
            *(float2*)(O1 + nt * 8) =
                make_float2(acc[mi][nt][2] * inv[mi][1], acc[mi][nt][3] * inv[mi][1]);
        }
    }
}

extern "C" void kernel_launch(void* const* d_in, const int* in_sizes, int n_in,
                              void* d_out, int out_size)
{
    const float* logits = (const float*)d_in[0];
    const float* value  = (const float*)d_in[1];
    const float* sinks  = (const float*)d_in[2];
    float* out = (float*)d_out;

    convert_v_kernel<<<(HH * 1024 * 32) / 256, 256>>>(value);

    cudaFuncSetAttribute(attn_sink_kernel,
                         cudaFuncAttributeMaxDynamicSharedMemorySize, SMEM_BYTES);

    dim3 grid(SQ / BM, HH, 1);
    attn_sink_kernel<<<grid, 128, SMEM_BYTES>>>(logits, sinks, out);
}

// round 15
// speedup vs baseline: 1.9391x; 1.6290x over previous
#include <cuda_runtime.h>
#include <cstdint>
#include <cstddef>

#define HH   32
#define SQ   2048
#define SKK  2048
#define DHH  128
#define BM   128
#define BN   64
#define NTILES (SKK / BN)          // 32
#define VSTR2 132                  // uint32 stride per k2-row in smem (conflict-free LDS.128)
#define LOG2E 1.4426950408889634f

// two half2 V buffers of [32][VSTR2] uint32
#define SMEM_BYTES (2 * 32 * VSTR2 * 4)

// V scratch: k-interleaved half2, COLUMN-PERMUTED (n) and ROW-PLACED (sigma over k2):
//   pair p (mem k rows 2p,2p+1) stored at row sigma(p) = (p&~7) | ((p&7)>>1)+((p&1)<<2)
//   column n stored at position (n&7)*16 + (n>>3)
__device__ uint32_t Vh_g[(size_t)HH * (SKK / 2) * DHH];   // 16 MB

__device__ __forceinline__ float ex2f(float x) {
    float y;
    asm("ex2.approx.ftz.f32 %0, %1;" : "=f"(y) : "f"(x));
    return y;
}
// pack two fp32 -> half2 with 'lo' in low 16 bits (verified R6-R10)
__device__ __forceinline__ uint32_t packh2(float lo, float hi) {
    uint32_t d;
    asm("cvt.rn.f16x2.f32 %0, %1, %2;" : "=r"(d) : "f"(hi), "f"(lo));
    return d;
}
__device__ __forceinline__ void cp16(uint32_t dst, const void* src) {
    asm volatile("cp.async.cg.shared.global [%0], [%1], 16;\n" :: "r"(dst), "l"(src));
}

// ---- kernel 1: V fp32 -> permuted interleaved half2 scratch ----
// Same as R10 except pair k2 lands at row sigma(k2) (keeps MMA B addressing identical
// to R10 while enabling float4 A loads via the matching k-permutation).
__global__ __launch_bounds__(256)
void convert_v_kernel(const float* __restrict__ value)
{
    const int idx = blockIdx.x * 256 + threadIdx.x;
    const int lr = idx & 7;
    const int tt = (idx >> 3) & 3;
    const int k2 = (idx >> 5) & 1023;
    const int h  = idx >> 15;
    const float* v0 = value + ((size_t)h * SKK + 2 * (size_t)k2) * DHH;
    const float* v1 = v0 + DHH;
    const int n0 = tt * 32 + lr;
    uint4 o;
    o.x = packh2(v0[n0],      v1[n0]);
    o.y = packh2(v0[n0 + 8],  v1[n0 + 8]);
    o.z = packh2(v0[n0 + 16], v1[n0 + 16]);
    o.w = packh2(v0[n0 + 24], v1[n0 + 24]);
    const int q  = k2 & 7;
    const int sr = (k2 & ~7) | ((q >> 1) + ((q & 1) << 2));   // sigma(k2)
    *(uint4*)&Vh_g[((size_t)h * 1024 + sr) * DHH + lr * 16 + tt * 4] = o;
}

// ---- kernel 2: fused sink-softmax @ V ----
__global__ __launch_bounds__(128)
void attn_sink_kernel(const float* __restrict__ logits,
                      const float* __restrict__ sinks,
                      float* __restrict__ out)
{
    extern __shared__ uint32_t smemh[];   // [2][32][VSTR2]

    const int qt   = blockIdx.x;
    const int h    = blockIdx.y;
    const int tid  = threadIdx.x;
    const int lane = tid & 31;
    const int w    = tid >> 5;        // warp 0..3 owns rows [w*32, w*32+32)
    const int lc   = lane & 3;
    const int lr   = lane >> 2;
    const int lc4  = 4 * lc;          // float4 A-column base (k-permutation pi)

    const float* Lg = logits + ((size_t)h * SQ + (size_t)qt * BM) * SKK;

    const uint32_t sbase = (uint32_t)__cvta_generic_to_shared(smemh);

    // A row pointers: [mi*2 + {0:r0, 1:r0+8}]
    const float* Ar[4];
#pragma unroll
    for (int mi = 0; mi < 2; ++mi) {
        const int r0 = w * 32 + mi * 16 + lr;
        Ar[mi * 2]     = Lg + (size_t)r0 * SKK;
        Ar[mi * 2 + 1] = Lg + (size_t)(r0 + 8) * SKK;
    }

    // ---- V staging (identical to R10): thread -> k2-row tid>>2, quarter (tid&3)*32 ----
    const int k2l = tid >> 2, nq = tid & 3;
    const uint32_t* Vsrc0 = &Vh_g[((size_t)h * 1024 + k2l) * DHH + nq * 32];
    const uint32_t Vdst0 = sbase + (uint32_t)(k2l * VSTR2 + nq * 32) * 4u;

#define STAGE_V(stg, ktn)                                                          \
    do {                                                                           \
        const uint32_t* s_ = Vsrc0 + (size_t)(ktn) * 32 * DHH;                     \
        uint32_t d_ = Vdst0 + (uint32_t)((stg) * 32 * VSTR2) * 4u;                 \
        _Pragma("unroll")                                                          \
        for (int i_ = 0; i_ < 8; ++i_) cp16(d_ + i_ * 16u, s_ + i_ * 4);           \
        asm volatile("cp.async.commit_group;\n");                                  \
    } while (0)

    STAGE_V(0, 0);

    float4 rawA[8], rawB[8];

    // A loads: ONE float4 per (mi,kk,row) — mem cols kk*16 + 4lc..4lc+3 carry
    // mma k {2lc, 2lc+1, 2lc+8, 2lc+9} under permutation pi
#define LDG_A(dst, h_, ktn)                                                        \
    do {                                                                           \
        _Pragma("unroll")                                                          \
        for (int mi_ = 0; mi_ < 2; ++mi_)                                          \
        _Pragma("unroll")                                                          \
        for (int kk_ = 0; kk_ < 2; ++kk_) {                                        \
            const int c_ = (ktn) * BN + ((h_) * 2 + kk_) * 16 + lc4;               \
            dst[(mi_ * 2 + kk_) * 2 + 0] = *(const float4*)(Ar[mi_ * 2]     + c_); \
            dst[(mi_ * 2 + kk_) * 2 + 1] = *(const float4*)(Ar[mi_ * 2 + 1] + c_); \
        }                                                                          \
    } while (0)

#define EXP_PACK(raw, P)                                                           \
    do {                                                                           \
        _Pragma("unroll")                                                          \
        for (int mi_ = 0; mi_ < 2; ++mi_)                                          \
        _Pragma("unroll")                                                          \
        for (int kk_ = 0; kk_ < 2; ++kk_) {                                        \
            float4 y0 = raw[(mi_ * 2 + kk_) * 2 + 0];                              \
            float4 y1 = raw[(mi_ * 2 + kk_) * 2 + 1];                              \
            float e00 = ex2f(y0.x * LOG2E), e01 = ex2f(y0.y * LOG2E);              \
            float e20 = ex2f(y0.z * LOG2E), e21 = ex2f(y0.w * LOG2E);              \
            float e10 = ex2f(y1.x * LOG2E), e11 = ex2f(y1.y * LOG2E);              \
            float e30 = ex2f(y1.z * LOG2E), e31 = ex2f(y1.w * LOG2E);              \
            psum[mi_][0] += (e00 + e01) + (e20 + e21);                             \
            psum[mi_][1] += (e10 + e11) + (e30 + e31);                             \
            P[mi_][kk_][0] = packh2(e00, e01);                                     \
            P[mi_][kk_][1] = packh2(e10, e11);                                     \
            P[mi_][kk_][2] = packh2(e20, e21);                                     \
            P[mi_][kk_][3] = packh2(e30, e31);                                     \
        }                                                                          \
    } while (0)

    // B via LDS.128 — BYTE-IDENTICAL to R10 (sigma placement preserves addressing)
#define MMA_HALF(P, kbase)                                                         \
    do {                                                                           \
        _Pragma("unroll")                                                          \
        for (int kk_ = 0; kk_ < 2; ++kk_) {                                        \
            const uint32_t* vr0 = &Vs[(((kbase) + kk_) * 8 + lc) * VSTR2 + lr * 16]; \
            const uint32_t* vr1 = vr0 + 4 * VSTR2;                                 \
            _Pragma("unroll")                                                      \
            for (int g_ = 0; g_ < 4; ++g_) {                                       \
                uint4 B0 = *(const uint4*)(vr0 + g_ * 4);                          \
                uint4 B1 = *(const uint4*)(vr1 + g_ * 4);                          \
                const uint32_t b0a[4] = {B0.x, B0.y, B0.z, B0.w};                  \
                const uint32_t b1a[4] = {B1.x, B1.y, B1.z, B1.w};                  \
                _Pragma("unroll")                                                  \
                for (int e_ = 0; e_ < 4; ++e_) {                                   \
                    const int nt_ = g_ * 4 + e_;                                   \
                    _Pragma("unroll")                                              \
                    for (int mi_ = 0; mi_ < 2; ++mi_) {                            \
                        asm volatile(                                              \
                            "mma.sync.aligned.m16n8k16.row.col.f32.f16.f16.f32 "   \
                            "{%0,%1,%2,%3}, {%4,%5,%6,%7}, {%8,%9}, {%0,%1,%2,%3};\n" \
                            : "+f"(acc[mi_][nt_][0]), "+f"(acc[mi_][nt_][1]),      \
                              "+f"(acc[mi_][nt_][2]), "+f"(acc[mi_][nt_][3])       \
                            : "r"(P[mi_][kk_][0]), "r"(P[mi_][kk_][1]),            \
                              "r"(P[mi_][kk_][2]), "r"(P[mi_][kk_][3]),            \
                              "r"(b0a[e_]), "r"(b1a[e_]));                         \
                    }                                                              \
                }                                                                  \
            }                                                                      \
        }                                                                          \
    } while (0)

    float acc[2][16][4];
#pragma unroll
    for (int mi = 0; mi < 2; ++mi)
#pragma unroll
        for (int nt = 0; nt < 16; ++nt) {
            acc[mi][nt][0] = 0.f; acc[mi][nt][1] = 0.f;
            acc[mi][nt][2] = 0.f; acc[mi][nt][3] = 0.f;
        }
    float psum[2][2] = {{0.f, 0.f}, {0.f, 0.f}};

    LDG_A(rawA, 0, 0);
    LDG_A(rawB, 1, 0);

    for (int kt = 0; kt < NTILES; ++kt) {
        const int cur = kt & 1;

        __syncthreads();   // readers of buf[cur^1] (prev iter) done before refill

        if (kt + 1 < NTILES) {
            STAGE_V(cur ^ 1, kt + 1);
            asm volatile("cp.async.wait_group 1;\n");
        } else {
            asm volatile("cp.async.wait_group 0;\n");
        }
        __syncthreads();   // buf[cur] visible

        const uint32_t* Vs = smemh + cur * 32 * VSTR2;

        uint32_t P[2][2][4];

        EXP_PACK(rawA, P);
        if (kt + 1 < NTILES) LDG_A(rawA, 0, kt + 1);
        MMA_HALF(P, 0);

        EXP_PACK(rawB, P);
        if (kt + 1 < NTILES) LDG_A(rawB, 1, kt + 1);
        MMA_HALF(P, 2);
    }

    // ---- reduce row sums over the quad, add sink, normalize ----
#pragma unroll
    for (int mi = 0; mi < 2; ++mi)
#pragma unroll
        for (int j = 0; j < 2; ++j) {
            psum[mi][j] += __shfl_xor_sync(0xffffffffu, psum[mi][j], 1);
            psum[mi][j] += __shfl_xor_sync(0xffffffffu, psum[mi][j], 2);
        }
    const float snk = ex2f(sinks[h] * LOG2E);
    float inv[2][2];
#pragma unroll
    for (int mi = 0; mi < 2; ++mi) {
        inv[mi][0] = 1.0f / (psum[mi][0] + snk);
        inv[mi][1] = 1.0f / (psum[mi][1] + snk);
    }

    float* Ob = out + ((size_t)h * SQ + (size_t)qt * BM) * DHH;
#pragma unroll
    for (int mi = 0; mi < 2; ++mi) {
        const int r0 = w * 32 + mi * 16 + lr;
        float* O0 = Ob + (size_t)r0 * DHH + 2 * lc;
        float* O1 = Ob + (size_t)(r0 + 8) * DHH + 2 * lc;
#pragma unroll
        for (int nt = 0; nt < 16; ++nt) {
            *(float2*)(O0 + nt * 8) =
                make_float2(acc[mi][nt][0] * inv[mi][0], acc[mi][nt][1] * inv[mi][0]);
            *(float2*)(O1 + nt * 8) =
                make_float2(acc[mi][nt][2] * inv[mi][1], acc[mi][nt][3] * inv[mi][1]);
        }
    }
}

extern "C" void kernel_launch(void* const* d_in, const int* in_sizes, int n_in,
                              void* d_out, int out_size)
{
    const float* logits = (const float*)d_in[0];
    const float* value  = (const float*)d_in[1];
    const float* sinks  = (const float*)d_in[2];
    float* out = (float*)d_out;

    convert_v_kernel<<<(HH * 1024 * 32) / 256, 256>>>(value);

    cudaFuncSetAttribute(attn_sink_kernel,
                         cudaFuncAttributeMaxDynamicSharedMemorySize, SMEM_BYTES);

    dim3 grid(SQ / BM, HH, 1);
    attn_sink_kernel<<<grid, 128, SMEM_BYTES>>>(logits, sinks, out);
}